// round 1
// baseline (speedup 1.0000x reference)
#include <cuda_runtime.h>
#include <stdint.h>

// Problem shape (fixed by the reference)
#define NT   4000
#define NS   16
#define NR   512
#define NSR  (NS * NR)          // 8192 columns
#define NCHUNK 10
#define TCHUNK (NT / NCHUNK)    // 400

// Scratch: per-column best (packed val|idx) for x and y, plus MSE accumulator.
// Packed u64 = (float_bits(v^2) << 32) | (NT-1-t). v^2 >= 0 so float bits are
// monotone; larger (NT-1-t) == smaller t wins ties -> argmax-first semantics.
__device__ unsigned long long g_best[2][NSR];
__device__ double g_sum;

__global__ void tt_init_kernel() {
    int i = blockIdx.x * blockDim.x + threadIdx.x;
    if (i < NSR) {
        g_best[0][i] = 0ull;
        g_best[1][i] = 0ull;
    }
    if (i == 0) g_sum = 0.0;
}

__global__ void tt_argmax_kernel(const float* __restrict__ x,
                                 const float* __restrict__ y) {
    const int col = blockIdx.x * blockDim.x + threadIdx.x;   // 32*256 = 8192
    const int t0  = blockIdx.y * TCHUNK;
    const int z   = blockIdx.z;                              // 0 = x, 1 = y
    const float* __restrict__ src =
        (z == 0 ? x : y) + (size_t)t0 * NSR + col;

    float best = -1.0f;
    int   bt   = t0;
#pragma unroll 8
    for (int i = 0; i < TCHUNK; i++) {
        float v  = src[(size_t)i * NSR];
        float v2 = v * v;
        if (v2 > best) { best = v2; bt = t0 + i; }   // strict '>' keeps first max
    }
    unsigned long long p =
        ((unsigned long long)__float_as_uint(best) << 32) |
        (unsigned int)(NT - 1 - bt);
    atomicMax(&g_best[z][col], p);
}

__global__ void tt_mse_kernel() {
    __shared__ double ssum[8];
    const int col  = blockIdx.x * blockDim.x + threadIdx.x;  // 32*256 = 8192
    const int lane = threadIdx.x & 31;
    const int wid  = threadIdx.x >> 5;

    int tx = NT - 1 - (int)(unsigned int)(g_best[0][col] & 0xffffffffull);
    int ty = NT - 1 - (int)(unsigned int)(g_best[1][col] & 0xffffffffull);
    float d = (float)tx - (float)ty;
    double v = (double)d * (double)d;

    // warp reduce
#pragma unroll
    for (int off = 16; off > 0; off >>= 1)
        v += __shfl_down_sync(0xffffffffu, v, off);
    if (lane == 0) ssum[wid] = v;
    __syncthreads();
    if (wid == 0) {
        double w = (lane < 8) ? ssum[lane] : 0.0;
#pragma unroll
        for (int off = 4; off > 0; off >>= 1)
            w += __shfl_down_sync(0xffffffffu, w, off);
        if (lane == 0) atomicAdd(&g_sum, w);
    }
}

__global__ void tt_finalize_kernel(float* __restrict__ out) {
    out[0] = (float)(g_sum * (1.0 / (double)NSR));
}

extern "C" void kernel_launch(void* const* d_in, const int* in_sizes, int n_in,
                              void* d_out, int out_size) {
    const float* x = (const float*)d_in[0];
    const float* y = (const float*)d_in[1];
    float* out = (float*)d_out;
    (void)in_sizes; (void)n_in; (void)out_size;

    tt_init_kernel<<<NSR / 256, 256>>>();

    dim3 grid(NSR / 256, NCHUNK, 2);
    tt_argmax_kernel<<<grid, 256>>>(x, y);

    tt_mse_kernel<<<NSR / 256, 256>>>();
    tt_finalize_kernel<<<1, 1>>>(out);
}